// round 13
// baseline (speedup 1.0000x reference)
#include <cuda_runtime.h>
#include <cuda_bf16.h>
#include <math_constants.h>

// out = x * (1 + sigmoid(max_{h,w} x)) per (b,c) plane; x: (32,512,56,56) fp32.
// The two channel shuffles in the reference are inverse permutations -> gate is
// just sigmoid of the per-plane max.
//
// Persistent-CTA version: grid = 148*8 resident CTAs, each loops over planes.
// Per plane: pass1 streams the 12.25KB plane from DRAM (caching in L1) and
// block-max-reduces; pass2 reloads from L1, scales, stores. While pass1's data
// is still in flight we issue prefetch.global.L2 for this CTA's NEXT plane so
// the DRAM queue stays fed during the reduce/barrier/store phases (this is the
// phase-lock bubble that held round-12 at 79.5% DRAM).

#define HW4 784        // 56*56/4 float4 per plane
#define THREADS 256
#define GRID (148 * 8)

__global__ __launch_bounds__(THREADS)
void dca_persist_kernel(const float4* __restrict__ x4,
                        float4* __restrict__ o4,
                        int planes) {
    __shared__ float wmax[8];
    __shared__ float scale_s;

    const int tid  = threadIdx.x;
    const int lane = tid & 31;
    const int wid  = tid >> 5;

    for (int p = blockIdx.x; p < planes; p += (int)gridDim.x) {
        const float4* __restrict__ xin  = x4 + (size_t)p * HW4;
        float4*       __restrict__ xout = o4 + (size_t)p * HW4;

        // ---- pass 1: stream plane, per-thread max (loads also warm L1) ----
        float4 a = xin[tid];
        float4 b = xin[tid + 256];
        float4 c = xin[tid + 512];
        float m = fmaxf(fmaxf(a.x, a.y), fmaxf(a.z, a.w));
        m = fmaxf(m, fmaxf(fmaxf(b.x, b.y), fmaxf(b.z, b.w)));
        m = fmaxf(m, fmaxf(fmaxf(c.x, c.y), fmaxf(c.z, c.w)));
        if (tid < HW4 - 768) {   // tid < 16
            float4 d = xin[tid + 768];
            m = fmaxf(m, fmaxf(fmaxf(d.x, d.y), fmaxf(d.z, d.w)));
        }

        // ---- prefetch next plane into L2 (98 x 128B lines), keeps DRAM busy
        //      through the reduce/barrier phase below ----
        {
            int np = p + (int)gridDim.x;
            if (np < planes && tid < 98) {
                const char* nptr =
                    (const char*)(x4 + (size_t)np * HW4) + (size_t)tid * 128;
                asm volatile("prefetch.global.L2 [%0];" :: "l"(nptr));
            }
        }

        // ---- block max reduce ----
        #pragma unroll
        for (int o = 16; o > 0; o >>= 1)
            m = fmaxf(m, __shfl_xor_sync(0xffffffffu, m, o));
        if (lane == 0) wmax[wid] = m;
        __syncthreads();
        if (wid == 0) {
            float t = (lane < 8) ? wmax[lane] : -CUDART_INF_F;
            #pragma unroll
            for (int o = 4; o > 0; o >>= 1)
                t = fmaxf(t, __shfl_xor_sync(0xffffffffu, t, o));
            if (lane == 0)
                scale_s = 1.0f + 1.0f / (1.0f + __expf(-t));
        }
        __syncthreads();
        const float s = scale_s;

        // ---- pass 2: reload (L1-resident), scale, store ----
        {
            float4 v = xin[tid];
            v.x *= s; v.y *= s; v.z *= s; v.w *= s;
            xout[tid] = v;
        }
        {
            float4 v = xin[tid + 256];
            v.x *= s; v.y *= s; v.z *= s; v.w *= s;
            xout[tid + 256] = v;
        }
        {
            float4 v = xin[tid + 512];
            v.x *= s; v.y *= s; v.z *= s; v.w *= s;
            xout[tid + 512] = v;
        }
        if (tid < HW4 - 768) {
            float4 v = xin[tid + 768];
            v.x *= s; v.y *= s; v.z *= s; v.w *= s;
            xout[tid + 768] = v;
        }
    }
}

extern "C" void kernel_launch(void* const* d_in, const int* in_sizes, int n_in,
                              void* d_out, int out_size) {
    const float4* x4 = (const float4*)d_in[0];
    float4* o4 = (float4*)d_out;
    const int planes = in_sizes[0] / (HW4 * 4);   // 16384 for this shape
    int grid = planes < GRID ? planes : GRID;
    dca_persist_kernel<<<grid, THREADS>>>(x4, o4, planes);
}